// round 2
// baseline (speedup 1.0000x reference)
#include <cuda_runtime.h>
#include <math.h>

#define NN 131072
#define EE 1048576
#define ET (EE + NN)

// ---------------- scratch (device globals: no runtime allocation) ----------
__device__ float g_bufA[(size_t)NN * 256];   // 128 MB ping
__device__ float g_bufB[(size_t)NN * 256];   // 128 MB pong
__device__ float g_as[NN * 4];
__device__ float g_ad[NN * 4];
__device__ int   g_rowptr[NN + 1];
__device__ int   g_cnt[NN];
__device__ int   g_csum[256];
__device__ int   g_col[ET];

// ---------------- embedding lookup ----------------
__global__ void k_embed(const int* __restrict__ x, const float* __restrict__ emb,
                        float* __restrict__ out) {
    int i = blockIdx.x * blockDim.x + threadIdx.x;
    if (i < NN * 64) out[i] = __ldg(&emb[x[i >> 6] * 64 + (i & 63)]);
}

// ---------------- CSR build ----------------
__global__ void k_zero_cnt() {
    int i = blockIdx.x * blockDim.x + threadIdx.x;
    if (i < NN) g_cnt[i] = 0;
}

__global__ void k_hist(const int* __restrict__ ei) {
    int e = blockIdx.x * blockDim.x + threadIdx.x;
    if (e >= ET) return;
    int dst = (e < EE) ? ei[EE + e] : (e - EE);
    atomicAdd(&g_cnt[dst], 1);
}

// chunk = 512 elems, 256 chunks
__global__ void k_chunk_sum() {
    __shared__ int sh[256];
    int b = blockIdx.x, t = threadIdx.x;
    sh[t] = g_cnt[b * 512 + t] + g_cnt[b * 512 + 256 + t];
    __syncthreads();
    for (int o = 128; o; o >>= 1) {
        if (t < o) sh[t] += sh[t + o];
        __syncthreads();
    }
    if (!t) g_csum[b] = sh[0];
}

__global__ void k_scan_chunks() {
    __shared__ int sh[256];
    int t = threadIdx.x;
    sh[t] = g_csum[t];
    __syncthreads();
    if (!t) {
        int run = 0;
        for (int i = 0; i < 256; i++) { int v = sh[i]; sh[i] = run; run += v; }
        g_rowptr[NN] = ET;
    }
    __syncthreads();
    g_csum[t] = sh[t];
}

__global__ void k_rowptr() {
    __shared__ int sh[512];
    int b = blockIdx.x, t = threadIdx.x;
    sh[t]       = g_cnt[b * 512 + t];
    sh[t + 256] = g_cnt[b * 512 + 256 + t];
    __syncthreads();
    if (!t) {
        int run = g_csum[b];
        for (int i = 0; i < 512; i++) { int v = sh[i]; sh[i] = run; run += v; }
    }
    __syncthreads();
    g_rowptr[b * 512 + t]       = sh[t];
    g_rowptr[b * 512 + 256 + t] = sh[t + 256];
}

__global__ void k_scatter(const int* __restrict__ ei) {
    int e = blockIdx.x * blockDim.x + threadIdx.x;
    if (e >= ET) return;
    int src, dst;
    if (e < EE) { src = ei[e]; dst = ei[EE + e]; }
    else        { src = dst = e - EE; }
    int pos = g_rowptr[dst] + atomicAdd(&g_cnt[dst], 1);
    g_col[pos] = src;
}

// ---------------- fp32 tiled GEMM: C[Nr,M] = A[Nr,K] @ B[K,M] ----------------
// block: 256 threads, tile 64x64, BK=16, thread micro-tile 4x4
__global__ void k_gemm(const float* __restrict__ A, const float* __restrict__ B,
                       float* __restrict__ C, int K, int M) {
    __shared__ float As[64][17];   // [row][k]
    __shared__ float Bs[16][64];   // [k][col]
    int tx = threadIdx.x & 15, ty = threadIdx.x >> 4;
    int row0 = blockIdx.y * 64, col0 = blockIdx.x * 64;
    float acc[4][4] = {};
    int r = threadIdx.x >> 4, kc = threadIdx.x & 15;   // A loader coords
    int kr = threadIdx.x >> 6, c = threadIdx.x & 63;   // B loader coords
    for (int k0 = 0; k0 < K; k0 += 16) {
#pragma unroll
        for (int i = 0; i < 4; i++)
            As[r + i * 16][kc] = A[(size_t)(row0 + r + i * 16) * K + k0 + kc];
#pragma unroll
        for (int i = 0; i < 4; i++)
            Bs[kr + i * 4][c] = B[(size_t)(k0 + kr + i * 4) * M + col0 + c];
        __syncthreads();
#pragma unroll
        for (int k = 0; k < 16; k++) {
            float a[4], b[4];
#pragma unroll
            for (int i = 0; i < 4; i++) a[i] = As[ty * 4 + i][k];
#pragma unroll
            for (int j = 0; j < 4; j++) b[j] = Bs[k][tx * 4 + j];
#pragma unroll
            for (int i = 0; i < 4; i++)
#pragma unroll
                for (int j = 0; j < 4; j++) acc[i][j] += a[i] * b[j];
        }
        __syncthreads();
    }
#pragma unroll
    for (int i = 0; i < 4; i++)
#pragma unroll
        for (int j = 0; j < 4; j++)
            C[(size_t)(row0 + ty * 4 + i) * M + col0 + tx * 4 + j] = acc[i][j];
}

// ---------------- per-node attention logits ----------------
// one warp per node; H heads of C=64
__global__ void k_alpha(const float* __restrict__ hfeat,
                        const float* __restrict__ a_src, const float* __restrict__ a_dst,
                        float* __restrict__ as_, float* __restrict__ ad_, int H) {
    int warp = (blockIdx.x * blockDim.x + threadIdx.x) >> 5;
    int lane = threadIdx.x & 31;
    if (warp >= NN) return;
    int F = H * 64;
    const float* hrow = hfeat + (size_t)warp * F;
    for (int h = 0; h < H; h++) {
        float v0 = hrow[h * 64 + lane], v1 = hrow[h * 64 + 32 + lane];
        float s = v0 * __ldg(&a_src[h * 64 + lane]) + v1 * __ldg(&a_src[h * 64 + 32 + lane]);
        float d = v0 * __ldg(&a_dst[h * 64 + lane]) + v1 * __ldg(&a_dst[h * 64 + 32 + lane]);
#pragma unroll
        for (int o = 16; o; o >>= 1) {
            s += __shfl_down_sync(0xffffffffu, s, o);
            d += __shfl_down_sync(0xffffffffu, d, o);
        }
        if (!lane) { as_[warp * H + h] = s; ad_[warp * H + h] = d; }
    }
}

// ---------------- gather aggregation, online softmax ----------------
// one warp per dst node. F = H*64 outputs, PER = F/32 per lane.
template <int H>
__global__ void k_aggregate(const float* __restrict__ hfeat,
                            const float* __restrict__ as_,
                            const float* __restrict__ ad_,
                            const float* __restrict__ bias,
                            float* __restrict__ out) {
    const int F = H * 64;
    const int PER = F / 32;
    int warp = (blockIdx.x * blockDim.x + threadIdx.x) >> 5;
    int lane = threadIdx.x & 31;
    if (warp >= NN) return;
    int d = warp;

    float adv[H], m[H], denom[H];
#pragma unroll
    for (int h = 0; h < H; h++) {
        adv[h] = __ldg(&ad_[(size_t)d * H + h]);
        m[h] = -1e30f;
        denom[h] = 0.f;
    }
    float acc[PER];
#pragma unroll
    for (int p = 0; p < PER; p++) acc[p] = 0.f;

    int beg = g_rowptr[d], end = g_rowptr[d + 1];
    for (int idx = beg; idx < end; idx++) {
        int s = __ldg(&g_col[idx]);
        float w[H], sc[H];
#pragma unroll
        for (int h = 0; h < H; h++) {
            float e = __ldg(&as_[(size_t)s * H + h]) + adv[h];
            e = e > 0.f ? e : 0.2f * e;         // leaky_relu 0.2
            float nm = fmaxf(m[h], e);
            sc[h] = __expf(m[h] - nm);
            w[h] = __expf(e - nm);
            denom[h] = denom[h] * sc[h] + w[h];
            m[h] = nm;
        }
        const float* hrow = hfeat + (size_t)s * F;
#pragma unroll
        for (int p = 0; p < PER; p++)
            acc[p] = acc[p] * sc[p >> 1] + w[p >> 1] * __ldg(&hrow[lane + p * 32]);
    }

    float* orow = out + (size_t)d * F;
#pragma unroll
    for (int p = 0; p < PER; p++) {
        int cidx = lane + p * 32;
        float v = acc[p] / (denom[p >> 1] + 1e-16f) + __ldg(&bias[cidx]);
        orow[cidx] = v > 0.f ? v : (expf(v) - 1.f);   // ELU
    }
}

// ---------------- final FC: [N,64] @ [64,5] + b ----------------
__global__ void k_fc(const float* __restrict__ in, const float* __restrict__ w,
                     const float* __restrict__ b, float* __restrict__ out) {
    int n = blockIdx.x * blockDim.x + threadIdx.x;
    if (n >= NN) return;
    const float4* hp = (const float4*)(in + (size_t)n * 64);
    float acc[5];
#pragma unroll
    for (int j = 0; j < 5; j++) acc[j] = __ldg(&b[j]);
#pragma unroll
    for (int k4 = 0; k4 < 16; k4++) {
        float4 v = hp[k4];
        float hv[4] = {v.x, v.y, v.z, v.w};
#pragma unroll
        for (int cc = 0; cc < 4; cc++) {
            int k = k4 * 4 + cc;
#pragma unroll
            for (int j = 0; j < 5; j++) acc[j] += hv[cc] * __ldg(&w[k * 5 + j]);
        }
    }
#pragma unroll
    for (int j = 0; j < 5; j++) out[(size_t)n * 5 + j] = acc[j];
}

// ---------------- launch ----------------
extern "C" void kernel_launch(void* const* d_in, const int* in_sizes, int n_in,
                              void* d_out, int out_size) {
    const int*   x   = (const int*)d_in[0];
    const int*   ei  = (const int*)d_in[1];
    const float* emb = (const float*)d_in[2];
    const float* W1  = (const float*)d_in[3];
    const float* a1s = (const float*)d_in[4];
    const float* a1d = (const float*)d_in[5];
    const float* b1  = (const float*)d_in[6];
    const float* W2  = (const float*)d_in[7];
    const float* a2s = (const float*)d_in[8];
    const float* a2d = (const float*)d_in[9];
    const float* b2  = (const float*)d_in[10];
    const float* W3  = (const float*)d_in[11];
    const float* a3s = (const float*)d_in[12];
    const float* a3d = (const float*)d_in[13];
    const float* b3  = (const float*)d_in[14];
    const float* fcw = (const float*)d_in[15];
    const float* fcb = (const float*)d_in[16];
    float* out = (float*)d_out;

    float *bufA, *bufB, *as_, *ad_;
    cudaGetSymbolAddress((void**)&bufA, g_bufA);
    cudaGetSymbolAddress((void**)&bufB, g_bufB);
    cudaGetSymbolAddress((void**)&as_, g_as);
    cudaGetSymbolAddress((void**)&ad_, g_ad);

    // embedding -> bufA [N,64]
    k_embed<<<(NN * 64) / 256, 256>>>(x, emb, bufA);

    // CSR by dst (reused by all 3 layers)
    k_zero_cnt<<<NN / 256, 256>>>();
    k_hist<<<ET / 256, 256>>>(ei);
    k_chunk_sum<<<256, 256>>>();
    k_scan_chunks<<<1, 256>>>();
    k_rowptr<<<256, 256>>>();
    k_zero_cnt<<<NN / 256, 256>>>();
    k_scatter<<<ET / 256, 256>>>(ei);

    const int aggBlocks = (NN * 32) / 256;   // one warp per node

    // ---- layer 1: in 64 -> H=4,C=64 concat (256) ----
    { dim3 g(256 / 64, NN / 64); k_gemm<<<g, 256>>>(bufA, W1, bufB, 64, 256); }
    k_alpha<<<aggBlocks, 256>>>(bufB, a1s, a1d, as_, ad_, 4);
    k_aggregate<4><<<aggBlocks, 256>>>(bufB, as_, ad_, b1, bufA);

    // ---- layer 2: 256 -> H=4,C=64 concat (256) ----
    { dim3 g(256 / 64, NN / 64); k_gemm<<<g, 256>>>(bufA, W2, bufB, 256, 256); }
    k_alpha<<<aggBlocks, 256>>>(bufB, a2s, a2d, as_, ad_, 4);
    k_aggregate<4><<<aggBlocks, 256>>>(bufB, as_, ad_, b2, bufA);

    // ---- layer 3: 256 -> H=1,C=64 (mean over 1 head = identity) ----
    { dim3 g(64 / 64, NN / 64); k_gemm<<<g, 256>>>(bufA, W3, bufB, 256, 64); }
    k_alpha<<<aggBlocks, 256>>>(bufB, a3s, a3d, as_, ad_, 1);
    k_aggregate<1><<<aggBlocks, 256>>>(bufB, as_, ad_, b3, bufA);

    // ---- FC head -> [N,5] ----
    k_fc<<<NN / 256, 256>>>(bufA, fcw, fcb, out);
}

// round 4
// speedup vs baseline: 1.0898x; 1.0898x over previous
#include <cuda_runtime.h>
#include <cstdint>
#include <math.h>

#define NN 131072
#define EE 1048576
#define ET (EE + NN)

// ---------------- scratch (device globals: no runtime allocation) ----------
__device__ float g_bufA[(size_t)NN * 256];   // 128 MB ping
__device__ float g_bufB[(size_t)NN * 256];   // 128 MB pong
__device__ float g_as[NN * 4];
__device__ float g_ad[NN * 4];
__device__ int   g_rowptr[NN + 1];
__device__ int   g_cnt[NN];
__device__ int   g_csum[256];
__device__ int   g_col[ET];

// packed dual-fp32 FMA: d = a*b + d (lane-wise on 2x f32)
__device__ __forceinline__ void ffma2(uint64_t& d, uint64_t a, uint64_t b) {
    asm("fma.rn.f32x2 %0, %1, %2, %0;" : "+l"(d) : "l"(a), "l"(b));
}
__device__ __forceinline__ uint64_t bcast2(float v) {
    uint64_t r;
    asm("mov.b64 %0, {%1, %1};" : "=l"(r) : "f"(v));
    return r;
}

// ---------------- embedding lookup ----------------
__global__ void k_embed(const int* __restrict__ x, const float* __restrict__ emb,
                        float* __restrict__ out) {
    int i = blockIdx.x * blockDim.x + threadIdx.x;
    if (i < NN * 64) out[i] = __ldg(&emb[x[i >> 6] * 64 + (i & 63)]);
}

// ---------------- CSR build ----------------
__global__ void k_zero_cnt() {
    int i = blockIdx.x * blockDim.x + threadIdx.x;
    if (i < NN) g_cnt[i] = 0;
}
__global__ void k_hist(const int* __restrict__ ei) {
    int e = blockIdx.x * blockDim.x + threadIdx.x;
    if (e >= ET) return;
    int dst = (e < EE) ? ei[EE + e] : (e - EE);
    atomicAdd(&g_cnt[dst], 1);
}
__global__ void k_chunk_sum() {
    __shared__ int sh[256];
    int b = blockIdx.x, t = threadIdx.x;
    sh[t] = g_cnt[b * 512 + t] + g_cnt[b * 512 + 256 + t];
    __syncthreads();
    for (int o = 128; o; o >>= 1) {
        if (t < o) sh[t] += sh[t + o];
        __syncthreads();
    }
    if (!t) g_csum[b] = sh[0];
}
__global__ void k_scan_chunks() {
    __shared__ int sh[256];
    int t = threadIdx.x;
    sh[t] = g_csum[t];
    __syncthreads();
    if (!t) {
        int run = 0;
        for (int i = 0; i < 256; i++) { int v = sh[i]; sh[i] = run; run += v; }
        g_rowptr[NN] = ET;
    }
    __syncthreads();
    g_csum[t] = sh[t];
}
__global__ void k_rowptr() {
    __shared__ int sh[512];
    int b = blockIdx.x, t = threadIdx.x;
    sh[t]       = g_cnt[b * 512 + t];
    sh[t + 256] = g_cnt[b * 512 + 256 + t];
    __syncthreads();
    if (!t) {
        int run = g_csum[b];
        for (int i = 0; i < 512; i++) { int v = sh[i]; sh[i] = run; run += v; }
    }
    __syncthreads();
    g_rowptr[b * 512 + t]       = sh[t];
    g_rowptr[b * 512 + 256 + t] = sh[t + 256];
}
__global__ void k_scatter(const int* __restrict__ ei) {
    int e = blockIdx.x * blockDim.x + threadIdx.x;
    if (e >= ET) return;
    int src, dst;
    if (e < EE) { src = ei[e]; dst = ei[EE + e]; }
    else        { src = dst = e - EE; }
    int pos = g_rowptr[dst] + atomicAdd(&g_cnt[dst], 1);
    g_col[pos] = src;
}

// ======== fp32 GEMM with packed f32x2 FMA: C[Nr,M] = A[Nr,K] @ B[K,M] ========
// CTA tile: 128 rows x TN cols, 256 threads (16x16 grid), microtile 8 x (TN/16).
// BK = 16. A stored k-major in smem so both operand fetches are LDS.128.
template <int TN>
__global__ void k_gemm(const float* __restrict__ A, const float* __restrict__ B,
                       float* __restrict__ C, int K, int M) {
    const int NI = TN / 16;       // cols per thread (8 or 4)
    const int NP = NI / 2;        // f32x2 pairs per thread row
    __shared__ float As[16][136]; // [k][row], padded
    __shared__ float Bs[16][TN];  // [k][col]

    int tid = threadIdx.x;
    int tx = tid & 15, ty = tid >> 4;
    int row0 = blockIdx.y * 128, col0 = blockIdx.x * TN;

    uint64_t acc[8][NP];
#pragma unroll
    for (int i = 0; i < 8; i++)
#pragma unroll
        for (int j = 0; j < NP; j++) acc[i][j] = 0ull;

    // A loader: row = tid>>1 (0..127), kq = (tid&1)*8, 2x float4 in k
    int a_row = tid >> 1, a_kq = (tid & 1) * 8;
    // B loader: flat float4 index
    const int B_VECS = 16 * TN / 4;   // 512 or 256

    for (int k0 = 0; k0 < K; k0 += 16) {
        // load A tile (transpose into k-major)
        float4 av0 = *(const float4*)(A + (size_t)(row0 + a_row) * K + k0 + a_kq);
        float4 av1 = *(const float4*)(A + (size_t)(row0 + a_row) * K + k0 + a_kq + 4);
        As[a_kq + 0][a_row] = av0.x; As[a_kq + 1][a_row] = av0.y;
        As[a_kq + 2][a_row] = av0.z; As[a_kq + 3][a_row] = av0.w;
        As[a_kq + 4][a_row] = av1.x; As[a_kq + 5][a_row] = av1.y;
        As[a_kq + 6][a_row] = av1.z; As[a_kq + 7][a_row] = av1.w;
        // load B tile (already k-major)
#pragma unroll
        for (int it = 0; it < B_VECS / 256; it++) {
            int idx = tid + it * 256;
            int bk = idx / (TN / 4), bc = (idx % (TN / 4)) * 4;
            *(float4*)&Bs[bk][bc] = *(const float4*)(B + (size_t)(k0 + bk) * M + col0 + bc);
        }
        __syncthreads();
#pragma unroll
        for (int k = 0; k < 16; k++) {
            float4 a0 = *(const float4*)&As[k][ty * 8];
            float4 a1 = *(const float4*)&As[k][ty * 8 + 4];
            uint64_t bp[NP];
#pragma unroll
            for (int j = 0; j < NP; j++)
                bp[j] = *(const uint64_t*)&Bs[k][tx * NI + j * 2];
            float ar[8] = {a0.x, a0.y, a0.z, a0.w, a1.x, a1.y, a1.z, a1.w};
#pragma unroll
            for (int i = 0; i < 8; i++) {
                uint64_t ai = bcast2(ar[i]);
#pragma unroll
                for (int j = 0; j < NP; j++) ffma2(acc[i][j], ai, bp[j]);
            }
        }
        __syncthreads();
    }
#pragma unroll
    for (int i = 0; i < 8; i++) {
        float* cp = C + (size_t)(row0 + ty * 8 + i) * M + col0 + tx * NI;
#pragma unroll
        for (int j = 0; j < NP; j++)
            *(float2*)(cp + j * 2) = *(float2*)&acc[i][j];
    }
}

// ---------------- per-node attention logits ----------------
__global__ void k_alpha(const float* __restrict__ hfeat,
                        const float* __restrict__ a_src, const float* __restrict__ a_dst,
                        float* __restrict__ as_, float* __restrict__ ad_, int H) {
    int warp = (blockIdx.x * blockDim.x + threadIdx.x) >> 5;
    int lane = threadIdx.x & 31;
    if (warp >= NN) return;
    int F = H * 64;
    const float* hrow = hfeat + (size_t)warp * F;
    for (int h = 0; h < H; h++) {
        float v0 = hrow[h * 64 + lane], v1 = hrow[h * 64 + 32 + lane];
        float s = v0 * __ldg(&a_src[h * 64 + lane]) + v1 * __ldg(&a_src[h * 64 + 32 + lane]);
        float d = v0 * __ldg(&a_dst[h * 64 + lane]) + v1 * __ldg(&a_dst[h * 64 + 32 + lane]);
#pragma unroll
        for (int o = 16; o; o >>= 1) {
            s += __shfl_down_sync(0xffffffffu, s, o);
            d += __shfl_down_sync(0xffffffffu, d, o);
        }
        if (!lane) { as_[warp * H + h] = s; ad_[warp * H + h] = d; }
    }
}

// ---------------- gather aggregation, online softmax ----------------
template <int H>
__global__ void k_aggregate(const float* __restrict__ hfeat,
                            const float* __restrict__ as_,
                            const float* __restrict__ ad_,
                            const float* __restrict__ bias,
                            float* __restrict__ out) {
    const int F = H * 64;
    const int PER = F / 32;
    int warp = (blockIdx.x * blockDim.x + threadIdx.x) >> 5;
    int lane = threadIdx.x & 31;
    if (warp >= NN) return;
    int d = warp;

    float adv[H], m[H], denom[H];
#pragma unroll
    for (int h = 0; h < H; h++) {
        adv[h] = __ldg(&ad_[(size_t)d * H + h]);
        m[h] = -1e30f;
        denom[h] = 0.f;
    }
    float acc[PER];
#pragma unroll
    for (int p = 0; p < PER; p++) acc[p] = 0.f;

    int beg = g_rowptr[d], end = g_rowptr[d + 1];
    for (int idx = beg; idx < end; idx++) {
        int s = __ldg(&g_col[idx]);
        float w[H], sc[H];
#pragma unroll
        for (int h = 0; h < H; h++) {
            float e = __ldg(&as_[(size_t)s * H + h]) + adv[h];
            e = e > 0.f ? e : 0.2f * e;         // leaky_relu 0.2
            float nm = fmaxf(m[h], e);
            sc[h] = __expf(m[h] - nm);
            w[h] = __expf(e - nm);
            denom[h] = denom[h] * sc[h] + w[h];
            m[h] = nm;
        }
        const float* hrow = hfeat + (size_t)s * F;
#pragma unroll
        for (int p = 0; p < PER; p++)
            acc[p] = acc[p] * sc[p >> 1] + w[p >> 1] * __ldg(&hrow[lane + p * 32]);
    }

    float* orow = out + (size_t)d * F;
#pragma unroll
    for (int p = 0; p < PER; p++) {
        int cidx = lane + p * 32;
        float v = acc[p] / (denom[p >> 1] + 1e-16f) + __ldg(&bias[cidx]);
        orow[cidx] = v > 0.f ? v : (expf(v) - 1.f);   // ELU
    }
}

// ---------------- final FC: [N,64] @ [64,5] + b ----------------
__global__ void k_fc(const float* __restrict__ in, const float* __restrict__ w,
                     const float* __restrict__ b, float* __restrict__ out) {
    int n = blockIdx.x * blockDim.x + threadIdx.x;
    if (n >= NN) return;
    const float4* hp = (const float4*)(in + (size_t)n * 64);
    float acc[5];
#pragma unroll
    for (int j = 0; j < 5; j++) acc[j] = __ldg(&b[j]);
#pragma unroll
    for (int k4 = 0; k4 < 16; k4++) {
        float4 v = hp[k4];
        float hv[4] = {v.x, v.y, v.z, v.w};
#pragma unroll
        for (int cc = 0; cc < 4; cc++) {
            int k = k4 * 4 + cc;
#pragma unroll
            for (int j = 0; j < 5; j++) acc[j] += hv[cc] * __ldg(&w[k * 5 + j]);
        }
    }
#pragma unroll
    for (int j = 0; j < 5; j++) out[(size_t)n * 5 + j] = acc[j];
}

// ---------------- launch ----------------
extern "C" void kernel_launch(void* const* d_in, const int* in_sizes, int n_in,
                              void* d_out, int out_size) {
    const int*   x   = (const int*)d_in[0];
    const int*   ei  = (const int*)d_in[1];
    const float* emb = (const float*)d_in[2];
    const float* W1  = (const float*)d_in[3];
    const float* a1s = (const float*)d_in[4];
    const float* a1d = (const float*)d_in[5];
    const float* b1  = (const float*)d_in[6];
    const float* W2  = (const float*)d_in[7];
    const float* a2s = (const float*)d_in[8];
    const float* a2d = (const float*)d_in[9];
    const float* b2  = (const float*)d_in[10];
    const float* W3  = (const float*)d_in[11];
    const float* a3s = (const float*)d_in[12];
    const float* a3d = (const float*)d_in[13];
    const float* b3  = (const float*)d_in[14];
    const float* fcw = (const float*)d_in[15];
    const float* fcb = (const float*)d_in[16];
    float* out = (float*)d_out;

    float *bufA, *bufB, *as_, *ad_;
    cudaGetSymbolAddress((void**)&bufA, g_bufA);
    cudaGetSymbolAddress((void**)&bufB, g_bufB);
    cudaGetSymbolAddress((void**)&as_, g_as);
    cudaGetSymbolAddress((void**)&ad_, g_ad);

    // embedding -> bufA [N,64]
    k_embed<<<(NN * 64) / 256, 256>>>(x, emb, bufA);

    // CSR by dst (reused by all 3 layers)
    k_zero_cnt<<<NN / 256, 256>>>();
    k_hist<<<ET / 256, 256>>>(ei);
    k_chunk_sum<<<256, 256>>>();
    k_scan_chunks<<<1, 256>>>();
    k_rowptr<<<256, 256>>>();
    k_zero_cnt<<<NN / 256, 256>>>();
    k_scatter<<<ET / 256, 256>>>(ei);

    const int aggBlocks = (NN * 32) / 256;   // one warp per node

    // ---- layer 1: in 64 -> H=4,C=64 concat (256) ----
    { dim3 g(256 / 128, NN / 128); k_gemm<128><<<g, 256>>>(bufA, W1, bufB, 64, 256); }
    k_alpha<<<aggBlocks, 256>>>(bufB, a1s, a1d, as_, ad_, 4);
    k_aggregate<4><<<aggBlocks, 256>>>(bufB, as_, ad_, b1, bufA);

    // ---- layer 2: 256 -> H=4,C=64 concat (256) ----
    { dim3 g(256 / 128, NN / 128); k_gemm<128><<<g, 256>>>(bufA, W2, bufB, 256, 256); }
    k_alpha<<<aggBlocks, 256>>>(bufB, a2s, a2d, as_, ad_, 4);
    k_aggregate<4><<<aggBlocks, 256>>>(bufB, as_, ad_, b2, bufA);

    // ---- layer 3: 256 -> H=1,C=64 (mean over 1 head = identity) ----
    { dim3 g(1, NN / 128); k_gemm<64><<<g, 256>>>(bufA, W3, bufB, 256, 64); }
    k_alpha<<<aggBlocks, 256>>>(bufB, a3s, a3d, as_, ad_, 1);
    k_aggregate<1><<<aggBlocks, 256>>>(bufB, as_, ad_, b3, bufA);

    // ---- FC head -> [N,5] ----
    k_fc<<<NN / 256, 256>>>(bufA, fcw, fcb, out);
}